// round 12
// baseline (speedup 1.0000x reference)
#include <cuda_runtime.h>
#include <cuda_fp16.h>
#include <cstdint>
#include <math.h>

// ----------------------------------------------------------------------------
// LorentzLinear R12: R11 + batched-LDSM inner loop.
//  Per iteration: issue all 12 ldmatrix (A ks0/ks1, B ks0, B ks1) before the
//  32 MMAs, so the smem crossbar pipelines 12 independent loads instead of
//  short load->use chains. Frag regs 48 + acc 64 = 112 < 128 (no spill).
// ----------------------------------------------------------------------------

#define THREADS 256
#define BM      64
#define KD      512
#define ND      512
#define KT      32
#define NTOT    32          // 2 chunks x 16 k-tiles
#define NST     3
#define NROWS   65536

// W scratch: 32 tiles x 16KB stage images, 16B units
__device__ uint4 g_wt[32 * 1024];

// smem layout (bytes)
#define OFF_APAN 0
#define APAN_SZ  (64 * 1024)
#define OFF_B    APAN_SZ
#define BST      16384
#define OFF_PART (OFF_B + NST * BST)
#define OFF_Y0T  (OFF_PART + 256)
#define SMEM_TOTAL (OFF_Y0T + 256)       // 115200 -> 2 CTAs = 230400

__device__ __forceinline__ uint32_t smem_u32(const void* p) {
    uint32_t a;
    asm("{ .reg .u64 t; cvta.to.shared.u64 t, %1; cvt.u32.u64 %0, t; }"
        : "=r"(a) : "l"(p));
    return a;
}

__device__ __forceinline__ void ldm4(uint32_t r[4], uint32_t addr) {
    asm volatile("ldmatrix.sync.aligned.m8n8.x4.shared.b16 {%0,%1,%2,%3}, [%4];"
                 : "=r"(r[0]), "=r"(r[1]), "=r"(r[2]), "=r"(r[3]) : "r"(addr));
}

__device__ __forceinline__ void mma16816(float c[4], const uint32_t a[4],
                                         uint32_t b0, uint32_t b1) {
    asm volatile(
        "mma.sync.aligned.m16n8k16.row.col.f32.f16.f16.f32 "
        "{%0,%1,%2,%3}, {%4,%5,%6,%7}, {%8,%9}, {%0,%1,%2,%3};"
        : "+f"(c[0]), "+f"(c[1]), "+f"(c[2]), "+f"(c[3])
        : "r"(a[0]), "r"(a[1]), "r"(a[2]), "r"(a[3]), "r"(b0), "r"(b1));
}

__device__ __forceinline__ void cp16(uint32_t smem_dst, const void* gsrc) {
    asm volatile("cp.async.cg.shared.global [%0], [%1], 16;"
                 :: "r"(smem_dst), "l"(gsrc));
}
#define CP_COMMIT() asm volatile("cp.async.commit_group;" ::: "memory")
#define CP_WAIT1()  asm volatile("cp.async.wait_group 1;" ::: "memory")

__device__ __forceinline__ void sts128(uint32_t addr, uint32_t r0, uint32_t r1,
                                       uint32_t r2, uint32_t r3) {
    asm volatile("st.shared.v4.b32 [%0], {%1,%2,%3,%4};"
                 :: "r"(addr), "r"(r0), "r"(r1), "r"(r2), "r"(r3) : "memory");
}

// ---------------- kernel A: W f32 -> fp16, tiled+swizzled stage images ------

__global__ void __launch_bounds__(256)
cvtW_kernel(const float* __restrict__ W) {
    const uint32_t u = blockIdx.x * 256 + threadIdx.x;
    if (u >= 32 * 1024) return;
    const uint32_t j   = u >> 10;
    const uint32_t off = (u & 1023) << 4;
    const uint32_t jj  = off >> 12;
    const uint32_t q   = off & 4095;
    const uint32_t p   = q >> 7;
    const uint32_t swz = (q >> 4) & 7;
    const uint32_t cu6 = swz ^ (p & 7);
    const uint32_t wrow = (j >> 4) * 256 + jj * 64 + p * 2 + (cu6 >> 2);
    const uint32_t k0   = (j & 15) * 32 + (cu6 & 3) * 8;
    const float* src = W + (size_t)wrow * KD + k0;
    float4 v0 = *reinterpret_cast<const float4*>(src);
    float4 v1 = *reinterpret_cast<const float4*>(src + 4);
    __half2 h[4];
    h[0] = __floats2half2_rn(v0.x, v0.y);
    h[1] = __floats2half2_rn(v0.z, v0.w);
    h[2] = __floats2half2_rn(v1.x, v1.y);
    h[3] = __floats2half2_rn(v1.z, v1.w);
    g_wt[u] = *reinterpret_cast<uint4*>(h);
}

// ---------------- main kernel ----------------

__global__ void __launch_bounds__(THREADS, 2)
lorentz_kernel(const float* __restrict__ x, const float* __restrict__ bias,
               const float* __restrict__ scale, float* __restrict__ out) {
    extern __shared__ char smem[];
    const uint32_t sb = smem_u32(smem);
    const int tid  = threadIdx.x;
    const int lane = tid & 31;
    const int w    = tid >> 5;
    const int wm   = w >> 2;
    const int wn   = w & 3;
    const int l15  = lane & 15;
    const int hi   = lane >> 4;
    const int row0 = blockIdx.x * BM;

    float* part = (float*)(smem + OFF_PART);
    float* y0t  = (float*)(smem + OFF_Y0T);

    if (tid < 64) part[tid] = 0.f;

    const uint32_t bDstL = sb + OFF_B + tid * 16;

    #define ISSUE(J) do {                                                     \
        const int _j = (J);                                                   \
        if (_j < NTOT) {                                                      \
            const int _st = _j % NST;                                         \
            const uint4* _src = g_wt + _j * 1024 + tid;                       \
            const uint32_t _d = bDstL + _st * BST;                            \
            _Pragma("unroll")                                                 \
            for (int _jj = 0; _jj < 4; ++_jj)                                 \
                cp16(_d + _jj * 4096, _src + _jj * 256);                      \
        }                                                                     \
        CP_COMMIT();                                                          \
    } while (0)

    ISSUE(0);
    ISSUE(1);

    // ---- A panel: convert 64x512 f32 -> fp16 smem ----
    #pragma unroll
    for (int i = 0; i < 16; ++i) {
        const int u   = tid + i * THREADS;
        const int row = u >> 6, cu = u & 63;
        const float* src = x + (size_t)(row0 + row) * KD + cu * 8;
        float4 v0 = *reinterpret_cast<const float4*>(src);
        float4 v1 = *reinterpret_cast<const float4*>(src + 4);
        __half2 h0 = __floats2half2_rn(v0.x, v0.y);
        __half2 h1 = __floats2half2_rn(v0.z, v0.w);
        __half2 h2 = __floats2half2_rn(v1.x, v1.y);
        __half2 h3 = __floats2half2_rn(v1.z, v1.w);
        const uint32_t dst = sb + OFF_APAN + row * 1024 + ((cu ^ (row & 7)) << 4);
        sts128(dst, *(uint32_t*)&h0, *(uint32_t*)&h1,
                    *(uint32_t*)&h2, *(uint32_t*)&h3);
    }
    __syncthreads();

    // ---- ldmatrix addressing ----
    const uint32_t aRow  = wm * 32 + l15;
    const uint32_t aBase = sb + OFF_APAN + aRow * 1024;
    const uint32_t ka    = aRow & 7;
    const uint32_t bBase = sb + OFF_B + (wn * 32 + (l15 >> 1)) * 128;
    const uint32_t kbm   = (l15 >> 1) & 7;
    const uint32_t bhb   = (l15 & 1) * 4;
    const uint32_t bxo0  = (((bhb + 0 + hi) ^ kbm) << 4);
    const uint32_t bxo1  = (((bhb + 2 + hi) ^ kbm) << 4);

    float acc[2][8][4];
    #pragma unroll
    for (int m = 0; m < 2; ++m)
        #pragma unroll
        for (int f = 0; f < 8; ++f)
            #pragma unroll
            for (int k = 0; k < 4; ++k) acc[m][f][k] = 0.f;

    // ---- flat mainloop ----
    #pragma unroll 1
    for (int j = 0; j < NTOT; ++j) {
        const int st = j % NST;
        CP_WAIT1();
        __syncthreads();
        ISSUE(j + 2);

        const uint32_t bS = bBase + st * BST;
        const uint32_t u0 = (uint32_t)((j & 15) * 4 + hi);

        // ---- batched LDSM: all 12 loads before any MMA ----
        uint32_t af[2][2][4];   // [ks][mblk]
        uint32_t bf[2][4][4];   // [ks][g]
        {
            const uint32_t axo0 = ((u0 ^ ka) << 4);
            const uint32_t axo1 = (((u0 + 2) ^ ka) << 4);
            ldm4(af[0][0], aBase + axo0);
            ldm4(af[0][1], aBase + 16 * 1024 + axo0);
            ldm4(af[1][0], aBase + axo1);
            ldm4(af[1][1], aBase + 16 * 1024 + axo1);
            #pragma unroll
            for (int g = 0; g < 4; ++g)
                ldm4(bf[0][g], bS + g * 1024 + bxo0);
            #pragma unroll
            for (int g = 0; g < 4; ++g)
                ldm4(bf[1][g], bS + g * 1024 + bxo1);
        }
        // ---- 32 MMAs ----
        #pragma unroll
        for (int ks = 0; ks < 2; ++ks) {
            #pragma unroll
            for (int g = 0; g < 4; ++g) {
                mma16816(acc[0][2 * g],     af[ks][0], bf[ks][g][0], bf[ks][g][2]);
                mma16816(acc[0][2 * g + 1], af[ks][0], bf[ks][g][1], bf[ks][g][3]);
                mma16816(acc[1][2 * g],     af[ks][1], bf[ks][g][0], bf[ks][g][2]);
                mma16816(acc[1][2 * g + 1], af[ks][1], bf[ks][g][1], bf[ks][g][3]);
            }
        }

        if (j == 15) {
            // ---- chunk-0 epilogue: bias, ssq, stash, reset ----
            float p[2][2] = {{0.f, 0.f}, {0.f, 0.f}};
            #pragma unroll
            for (int m = 0; m < 2; ++m) {
                #pragma unroll
                for (int f = 0; f < 8; ++f) {
                    const int col = wn * 64 + f * 8 + (lane & 3) * 2;
                    const float2 bv = __ldg(reinterpret_cast<const float2*>(bias + col));
                    acc[m][f][0] += bv.x; acc[m][f][1] += bv.y;
                    acc[m][f][2] += bv.x; acc[m][f][3] += bv.y;
                    p[m][0] += acc[m][f][0] * acc[m][f][0] + acc[m][f][1] * acc[m][f][1];
                    p[m][1] += acc[m][f][2] * acc[m][f][2] + acc[m][f][3] * acc[m][f][3];
                }
            }
            if (wn == 0 && (lane & 3) == 0) {
                #pragma unroll
                for (int m = 0; m < 2; ++m) {
                    p[m][0] -= acc[m][0][0] * acc[m][0][0];
                    p[m][1] -= acc[m][0][2] * acc[m][0][2];
                    y0t[wm * 32 + m * 16 + (lane >> 2)]     = acc[m][0][0];
                    y0t[wm * 32 + m * 16 + 8 + (lane >> 2)] = acc[m][0][2];
                }
            }
            #pragma unroll
            for (int m = 0; m < 2; ++m)
                #pragma unroll
                for (int h = 0; h < 2; ++h) {
                    float v = p[m][h];
                    v += __shfl_xor_sync(0xffffffffu, v, 1);
                    v += __shfl_xor_sync(0xffffffffu, v, 2);
                    if ((lane & 3) == 0)
                        atomicAdd(&part[wm * 32 + m * 16 + h * 8 + (lane >> 2)], v);
                }
            #pragma unroll
            for (int m = 0; m < 2; ++m) {
                const int rlo = wm * 32 + m * 16 + (lane >> 2);
                #pragma unroll
                for (int f = 0; f < 8; ++f) {
                    const int c = wn * 64 + f * 8 + (lane & 3) * 2;
                    *reinterpret_cast<float2*>(out + (size_t)(row0 + rlo) * ND + c) =
                        make_float2(acc[m][f][0], acc[m][f][1]);
                    *reinterpret_cast<float2*>(out + (size_t)(row0 + rlo + 8) * ND + c) =
                        make_float2(acc[m][f][2], acc[m][f][3]);
                }
            }
            #pragma unroll
            for (int m = 0; m < 2; ++m)
                #pragma unroll
                for (int f = 0; f < 8; ++f)
                    #pragma unroll
                    for (int k = 0; k < 4; ++k) acc[m][f][k] = 0.f;
        }
    }
    #undef ISSUE

    // ---- chunk-1 epilogue: bias + ssq ----
    {
        float p[2][2] = {{0.f, 0.f}, {0.f, 0.f}};
        #pragma unroll
        for (int m = 0; m < 2; ++m) {
            #pragma unroll
            for (int f = 0; f < 8; ++f) {
                const int col = 256 + wn * 64 + f * 8 + (lane & 3) * 2;
                const float2 bv = __ldg(reinterpret_cast<const float2*>(bias + col));
                acc[m][f][0] += bv.x; acc[m][f][1] += bv.y;
                acc[m][f][2] += bv.x; acc[m][f][3] += bv.y;
                p[m][0] += acc[m][f][0] * acc[m][f][0] + acc[m][f][1] * acc[m][f][1];
                p[m][1] += acc[m][f][2] * acc[m][f][2] + acc[m][f][3] * acc[m][f][3];
            }
        }
        #pragma unroll
        for (int m = 0; m < 2; ++m)
            #pragma unroll
            for (int h = 0; h < 2; ++h) {
                float v = p[m][h];
                v += __shfl_xor_sync(0xffffffffu, v, 1);
                v += __shfl_xor_sync(0xffffffffu, v, 2);
                if ((lane & 3) == 0)
                    atomicAdd(&part[wm * 32 + m * 16 + h * 8 + (lane >> 2)], v);
            }
    }
    __syncthreads();

    // ---- per-row scalars ----
    if (tid < 64) {
        const float tot = part[tid];
        const float y0 = y0t[tid];
        const float es = expf(scale[0]);
        const float t  = es / (1.f + expf(-y0)) + 1.1f;
        const float rr = sqrtf((t * t - 1.f) / fmaxf(tot, 1e-8f));
        part[tid] = rr;
        y0t[tid]  = t;
    }
    __syncthreads();

    // ---- write chunk 1 from registers, scaled ----
    #pragma unroll
    for (int m = 0; m < 2; ++m) {
        const int rlo = wm * 32 + m * 16 + (lane >> 2);
        const float rr0 = part[rlo], rr1 = part[rlo + 8];
        #pragma unroll
        for (int f = 0; f < 8; ++f) {
            const int c = 256 + wn * 64 + f * 8 + (lane & 3) * 2;
            *reinterpret_cast<float2*>(out + (size_t)(row0 + rlo) * ND + c) =
                make_float2(acc[m][f][0] * rr0, acc[m][f][1] * rr0);
            *reinterpret_cast<float2*>(out + (size_t)(row0 + rlo + 8) * ND + c) =
                make_float2(acc[m][f][2] * rr1, acc[m][f][3] * rr1);
        }
    }

    // ---- rescale chunk 0 in place (L2-hot) ----
    #pragma unroll 4
    for (int i = tid; i < 64 * 64; i += THREADS) {
        const int r  = i >> 6;
        const int c4 = (i & 63) * 4;
        const float rr = part[r];
        float* p4 = out + (size_t)(row0 + r) * ND + c4;
        float4 v = *reinterpret_cast<float4*>(p4);
        v.x *= rr; v.y *= rr; v.z *= rr; v.w *= rr;
        if (c4 == 0) v.x = y0t[r];
        *reinterpret_cast<float4*>(p4) = v;
    }
}

// ---------------- launch ----------------

extern "C" void kernel_launch(void* const* d_in, const int* in_sizes, int n_in,
                              void* d_out, int out_size) {
    const float* x     = (const float*)d_in[0];
    const float* W     = (const float*)d_in[1];
    const float* b     = (const float*)d_in[2];
    const float* scale = (const float*)d_in[3];
    float* out = (float*)d_out;

    cvtW_kernel<<<(32 * 1024 + 255) / 256, 256>>>(W);

    const int rows = in_sizes[0] / KD;     // 65536
    const int grid = rows / BM;            // 1024
    cudaFuncSetAttribute(lorentz_kernel,
                         cudaFuncAttributeMaxDynamicSharedMemorySize, SMEM_TOTAL);
    lorentz_kernel<<<grid, THREADS, SMEM_TOTAL>>>(x, b, scale, out);
}